// round 1
// baseline (speedup 1.0000x reference)
#include <cuda_runtime.h>

// SVConvTranspose2d: spatially-varying conv-transpose.
// x:      (N=4, CIN=16, H=128, W=128) f32
// weight: (CIN=16, COUT=16, KH=5, KW=5, H=128, W=128) f32   -- 419 MB, read-once stream
// bias:   (1, COUT, 1, 1) f32
// out:    (N=4, COUT=16, H=128, W=128) f32
//
// out[n,o,oh,ow] = bias[o] + sum_{kh,kw,i} x[n,i,h,w] * weight[i,o,kh,kw,h,w]
//   with h = oh+2-kh, w = ow+2-kw, valid taps only.
//
// Each thread owns one output pixel, one group of OG=8 output channels, and
// ALL 4 batches (acc[8][4]) so every weight element is loaded exactly once.

#define N_B   4
#define C_IN  16
#define C_OUT 16
#define KH_   5
#define KW_   5
#define H_    128
#define W_    128

constexpr int OG          = 8;                 // output channels per thread
constexpr int HW          = H_ * W_;           // 16384
constexpr int W_IO_STRIDE = KH_ * KW_ * HW;    // 409600 elems per (i,o) plane set

__global__ __launch_bounds__(64)
void svct_kernel(const float* __restrict__ x,
                 const float* __restrict__ wt,
                 const float* __restrict__ bias,
                 float* __restrict__ out)
{
    const int tid   = blockIdx.x * 64 + threadIdx.x;   // 32768 threads total
    const int og    = tid >> 14;                       // 0..1  (COUT/OG groups)
    const int pix   = tid & (HW - 1);
    const int oh    = pix >> 7;
    const int ow    = pix & (W_ - 1);
    const int obase = og * OG;

    float acc[OG][N_B];
    #pragma unroll
    for (int oo = 0; oo < OG; oo++)
        #pragma unroll
        for (int n = 0; n < N_B; n++)
            acc[oo][n] = 0.0f;

    #pragma unroll 1
    for (int kh = 0; kh < KH_; kh++) {
        const int h = oh + 2 - kh;
        if ((unsigned)h >= H_) continue;
        #pragma unroll 1
        for (int kw = 0; kw < KW_; kw++) {
            const int w = ow + 2 - kw;
            if ((unsigned)w >= W_) continue;

            const int sp  = h * W_ + w;
            const int tap = kh * KW_ + kw;
            const float* wp = wt + (long)obase * W_IO_STRIDE + (long)tap * HW + sp;
            const float* xp = x + sp;

            #pragma unroll 4
            for (int i = 0; i < C_IN; i++) {
                float xv[N_B];
                #pragma unroll
                for (int n = 0; n < N_B; n++)
                    xv[n] = __ldg(xp + (long)(n * C_IN + i) * HW);

                #pragma unroll
                for (int oo = 0; oo < OG; oo++) {
                    // streaming load: weight is a read-once 419MB stream,
                    // keep it from evicting the hot x planes in L2.
                    float wv = __ldcs(wp + (long)(i * C_OUT + oo) * W_IO_STRIDE);
                    #pragma unroll
                    for (int n = 0; n < N_B; n++)
                        acc[oo][n] = fmaf(wv, xv[n], acc[oo][n]);
                }
            }
        }
    }

    #pragma unroll
    for (int oo = 0; oo < OG; oo++) {
        const float b = __ldg(bias + obase + oo);
        #pragma unroll
        for (int n = 0; n < N_B; n++)
            out[((long)(n * C_OUT + obase + oo) * H_ + oh) * W_ + ow] = acc[oo][n] + b;
    }
}

extern "C" void kernel_launch(void* const* d_in, const int* in_sizes, int n_in,
                              void* d_out, int out_size)
{
    const float* x    = (const float*)d_in[0];
    const float* wt   = (const float*)d_in[1];
    const float* bias = (const float*)d_in[2];
    float*       out  = (float*)d_out;

    // 32768 threads = 128*128 pixels * 2 o-groups
    svct_kernel<<<512, 64>>>(x, wt, bias, out);
}

// round 2
// speedup vs baseline: 2.4466x; 2.4466x over previous
#include <cuda_runtime.h>

// SVConvTranspose2d, round 2: Cin split 4-way for 4x warp concurrency.
// x:      (4, 16, 128, 128) f32
// weight: (16, 16, 5, 5, 128, 128) f32  -- 419 MB, read exactly once
// bias:   (1, 16, 1, 1) f32
// out:    (4, 16, 128, 128) f32
//
// Block = 256 threads = 64 pixels x 4 i-slices (4 input channels each).
// Each thread: acc[8 outs][4 batches] over its 4 input channels.
// Smem tree-reduce the 4 slices, 64 threads write the block's outputs.

#define N_B   4
#define C_IN  16
#define C_OUT 16
#define KH_   5
#define KW_   5
#define H_    128
#define W_    128

constexpr int OG          = 8;               // output channels per thread
constexpr int IS          = 4;               // i-slices per block
constexpr int IPS         = C_IN / IS;       // input channels per slice = 4
constexpr int PIX_PER_BLK = 64;
constexpr int HW          = H_ * W_;         // 16384
constexpr int W_IO_STRIDE = KH_ * KW_ * HW;  // 409600

__global__ __launch_bounds__(256, 4)
void svct_kernel(const float* __restrict__ x,
                 const float* __restrict__ wt,
                 const float* __restrict__ bias,
                 float* __restrict__ out)
{
    // smem[j][slice][pixel], j = oo*4+n  -> conflict-free STS and LDS
    __shared__ float red[OG * N_B][IS][PIX_PER_BLK];

    const int s     = threadIdx.x >> 6;          // i-slice 0..3
    const int p     = threadIdx.x & 63;          // pixel lane 0..63
    const int og    = blockIdx.x >> 8;           // 0..1
    const int pix   = (blockIdx.x & 255) * PIX_PER_BLK + p;
    const int oh    = pix >> 7;
    const int ow    = pix & (W_ - 1);
    const int obase = og * OG;
    const int ibase = s * IPS;

    float acc[OG][N_B];
    #pragma unroll
    for (int oo = 0; oo < OG; oo++)
        #pragma unroll
        for (int n = 0; n < N_B; n++)
            acc[oo][n] = 0.0f;

    #pragma unroll 1
    for (int kh = 0; kh < KH_; kh++) {
        const int h = oh + 2 - kh;
        if ((unsigned)h >= H_) continue;
        #pragma unroll 1
        for (int kw = 0; kw < KW_; kw++) {
            const int w = ow + 2 - kw;
            if ((unsigned)w >= W_) continue;

            const int sp  = h * W_ + w;
            const int tap = kh * KW_ + kw;
            const float* wp = wt + (long)(ibase * C_OUT + obase) * W_IO_STRIDE
                                 + (long)tap * HW + sp;
            const float* xp = x + (long)ibase * HW + sp;

            #pragma unroll
            for (int i = 0; i < IPS; i++) {
                float xv[N_B];
                #pragma unroll
                for (int n = 0; n < N_B; n++)
                    xv[n] = __ldg(xp + (long)(n * C_IN + i) * HW);

                #pragma unroll
                for (int oo = 0; oo < OG; oo++) {
                    // streaming load: weight is a read-once 419MB stream
                    float wv = __ldcs(wp + (long)(i * C_OUT + oo) * W_IO_STRIDE);
                    #pragma unroll
                    for (int n = 0; n < N_B; n++)
                        acc[oo][n] = fmaf(wv, xv[n], acc[oo][n]);
                }
            }
        }
    }

    // dump partials to smem
    #pragma unroll
    for (int oo = 0; oo < OG; oo++)
        #pragma unroll
        for (int n = 0; n < N_B; n++)
            red[oo * N_B + n][s][p] = acc[oo][n];
    __syncthreads();

    // slice 0 threads combine the 4 slices and write out
    if (s == 0) {
        #pragma unroll
        for (int oo = 0; oo < OG; oo++) {
            const float b = __ldg(bias + obase + oo);
            #pragma unroll
            for (int n = 0; n < N_B; n++) {
                const int j = oo * N_B + n;
                float v = red[j][0][p] + red[j][1][p] + red[j][2][p] + red[j][3][p];
                out[((long)(n * C_OUT + obase + oo) * H_ + oh) * W_ + ow] = v + b;
            }
        }
    }
}

extern "C" void kernel_launch(void* const* d_in, const int* in_sizes, int n_in,
                              void* d_out, int out_size)
{
    const float* x    = (const float*)d_in[0];
    const float* wt   = (const float*)d_in[1];
    const float* bias = (const float*)d_in[2];
    float*       out  = (float*)d_out;

    svct_kernel<<<512, 256>>>(x, wt, bias, out);
}

// round 3
// speedup vs baseline: 4.0102x; 1.6391x over previous
#include <cuda_runtime.h>

// SVConvTranspose2d, round 3: OG=4 (half the accumulators), 2x warps.
// x:      (4, 16, 128, 128) f32       -- 4 MB, L2-resident
// weight: (16, 16, 5, 5, 128, 128) f32 -- 419 MB, read EXACTLY once
// bias:   (1, 16, 1, 1) f32
// out:    (4, 16, 128, 128) f32
//
// Block = 256 threads = 64 pixels x 4 i-slices (4 input channels each).
// Grid  = 256 pixel-blocks x 4 o-groups (4 out channels each) = 1024 blocks.
// Each thread: acc[4 outs][4 batches] (16 regs) -> room to batch 16 weight +
// 16 x loads per tap for deep MLP. Smem reduces the 4 i-slices.

#define N_B   4
#define C_IN  16
#define C_OUT 16
#define KH_   5
#define KW_   5
#define H_    128
#define W_    128

constexpr int OG          = 4;               // output channels per thread
constexpr int IS          = 4;               // i-slices per block
constexpr int IPS         = C_IN / IS;       // input channels per slice = 4
constexpr int PIX_PER_BLK = 64;
constexpr int HW          = H_ * W_;         // 16384
constexpr int W_IO_STRIDE = KH_ * KW_ * HW;  // 409600

__global__ __launch_bounds__(256, 4)
void svct_kernel(const float* __restrict__ x,
                 const float* __restrict__ wt,
                 const float* __restrict__ bias,
                 float* __restrict__ out)
{
    // smem[j][slice][pixel], j = oo*4+n -> conflict-free STS/LDS
    __shared__ float red[OG * N_B][IS][PIX_PER_BLK];

    const int s     = threadIdx.x >> 6;          // i-slice 0..3
    const int p     = threadIdx.x & 63;          // pixel lane 0..63
    const int og    = blockIdx.x >> 8;           // 0..3
    const int pix   = (blockIdx.x & 255) * PIX_PER_BLK + p;
    const int oh    = pix >> 7;
    const int ow    = pix & (W_ - 1);
    const int obase = og * OG;
    const int ibase = s * IPS;

    float acc[OG][N_B];
    #pragma unroll
    for (int oo = 0; oo < OG; oo++)
        #pragma unroll
        for (int n = 0; n < N_B; n++)
            acc[oo][n] = 0.0f;

    #pragma unroll 1
    for (int kh = 0; kh < KH_; kh++) {
        const int h = oh + 2 - kh;
        if ((unsigned)h >= H_) continue;
        #pragma unroll 1
        for (int kw = 0; kw < KW_; kw++) {
            const int w = ow + 2 - kw;
            if ((unsigned)w >= W_) continue;

            const int sp  = h * W_ + w;
            const int tap = kh * KW_ + kw;
            const float* wp = wt + (long)(ibase * C_OUT + obase) * W_IO_STRIDE
                                 + (long)tap * HW + sp;
            const float* xp = x + (long)ibase * HW + sp;

            // Batch all weight loads for this tap (16 independent lines),
            // then all x loads, then the FMA block. Keeps MLP deep.
            float wv[IPS][OG];
            #pragma unroll
            for (int i = 0; i < IPS; i++)
                #pragma unroll
                for (int oo = 0; oo < OG; oo++)
                    wv[i][oo] = __ldcs(wp + (long)(i * C_OUT + oo) * W_IO_STRIDE);

            float xv[IPS][N_B];
            #pragma unroll
            for (int i = 0; i < IPS; i++)
                #pragma unroll
                for (int n = 0; n < N_B; n++)
                    xv[i][n] = __ldg(xp + (long)(n * C_IN + i) * HW);

            #pragma unroll
            for (int i = 0; i < IPS; i++)
                #pragma unroll
                for (int oo = 0; oo < OG; oo++)
                    #pragma unroll
                    for (int n = 0; n < N_B; n++)
                        acc[oo][n] = fmaf(wv[i][oo], xv[i][n], acc[oo][n]);
        }
    }

    // dump partials to smem
    #pragma unroll
    for (int oo = 0; oo < OG; oo++)
        #pragma unroll
        for (int n = 0; n < N_B; n++)
            red[oo * N_B + n][s][p] = acc[oo][n];
    __syncthreads();

    // slice 0 threads combine the 4 slices and write out
    if (s == 0) {
        #pragma unroll
        for (int oo = 0; oo < OG; oo++) {
            const float b = __ldg(bias + obase + oo);
            #pragma unroll
            for (int n = 0; n < N_B; n++) {
                const int j = oo * N_B + n;
                float v = red[j][0][p] + red[j][1][p] + red[j][2][p] + red[j][3][p];
                out[((long)(n * C_OUT + obase + oo) * H_ + oh) * W_ + ow] = v + b;
            }
        }
    }
}

extern "C" void kernel_launch(void* const* d_in, const int* in_sizes, int n_in,
                              void* d_out, int out_size)
{
    const float* x    = (const float*)d_in[0];
    const float* wt   = (const float*)d_in[1];
    const float* bias = (const float*)d_in[2];
    float*       out  = (float*)d_out;

    svct_kernel<<<1024, 256>>>(x, wt, bias, out);
}

// round 4
// speedup vs baseline: 4.7624x; 1.1876x over previous
#include <cuda_runtime.h>

// SVConvTranspose2d, round 4: float4 weight stream + warp-shuffle kw scatter.
//
// x:      (4, 16, 128, 128) f32        -- 4 MB, L2-hot
// weight: (16, 16, 5, 5, 128, 128) f32 -- 419 MB, read EXACTLY once, LDG.128
// bias:   (1, 16, 1, 1) f32
// out:    (4, 16, 128, 128) f32
//
// out[n,o,oh,ow] = bias[o] + sum_{kh,kw,i} x[n,i,h,w] * wt[i,o,kh,kw,h,w]
//   h = oh+2-kh, w = ow+2-kw (valid only).
//
// Thread owns ALIGNED output quad ow in [4q, 4q+4). For tap kw it needs
// weight/x at w = ow+2-kw, i.e. an 8-wide window [4q-2, 4q+6) built from the
// thread's own aligned quad plus 2 elems from each neighbor lane via shuffle.
// A warp spans one full 128-wide row, so warp edges == image edges (mask by
// zeroing the spilled weight values at lanes 0 / 31).
//
// Block = 256 thr = (ih:4 i-slices of 4) x (o2:2 outs) x (q:32 quads).
// Grid  = 128 rows x 8 o-pairs = 1024 blocks. Smem reduces the 4 i-slices.

#define H_    128
#define W_    128
#define HW    16384

__global__ __launch_bounds__(256)
void svct_kernel(const float* __restrict__ x,
                 const float* __restrict__ wt,
                 const float* __restrict__ bias,
                 float* __restrict__ out)
{
    __shared__ float red[2][4][4][W_];   // [o2][n][ih][w]  16 KB

    const int t   = threadIdx.x;
    const int q   = t & 31;              // quad index in row
    const int o2  = (t >> 5) & 1;        // which of the 2 outs
    const int ih  = t >> 6;              // i-slice 0..3
    const int oh  = blockIdx.x >> 3;     // output row
    const int og  = blockIdx.x & 7;      // o-pair
    const int oc  = og * 2 + o2;         // output channel
    const int ibase = ih * 4;

    const bool q0  = (q == 0);
    const bool q31 = (q == 31);

    float acc[4][4];                     // [n][j]
    #pragma unroll
    for (int n = 0; n < 4; n++)
        #pragma unroll
        for (int j = 0; j < 4; j++)
            acc[n][j] = 0.0f;

    #pragma unroll 1
    for (int kh = 0; kh < 5; kh++) {
        const int h = oh + 2 - kh;
        if ((unsigned)h >= (unsigned)H_) continue;

        #pragma unroll 1
        for (int ii = 0; ii < 4; ii++) {
            const int i = ibase + ii;

            // ---- x quads (aligned float4, L1/L2-hot) + window extensions
            float4 xq[4];
            #pragma unroll
            for (int n = 0; n < 4; n++)
                xq[n] = __ldg((const float4*)x + ((n * 16 + i) * H_ + h) * 32 + q);

            float xp2[4], xp3[4], xn0[4], xn1[4];
            #pragma unroll
            for (int n = 0; n < 4; n++) {
                xp2[n] = __shfl_up_sync(0xffffffffu, xq[n].z, 1);
                xp3[n] = __shfl_up_sync(0xffffffffu, xq[n].w, 1);
                xn0[n] = __shfl_down_sync(0xffffffffu, xq[n].x, 1);
                xn1[n] = __shfl_down_sync(0xffffffffu, xq[n].y, 1);
            }

            // ---- 5 weight quads (one per kw plane), streaming float4
            const long wrow = ((long)((i * 16 + oc) * 5 + kh) * 5) * HW + (long)h * W_;

            #pragma unroll
            for (int kw = 0; kw < 5; kw++) {
                float4 w4 = __ldcs((const float4*)(wt + wrow + (long)kw * HW) + q);

                float wp2 = __shfl_up_sync(0xffffffffu, w4.z, 1);
                float wp3 = __shfl_up_sync(0xffffffffu, w4.w, 1);
                float wn0 = __shfl_down_sync(0xffffffffu, w4.x, 1);
                float wn1 = __shfl_down_sync(0xffffffffu, w4.y, 1);
                if (q0)  { wp2 = 0.0f; wp3 = 0.0f; }   // w-pos < 0
                if (q31) { wn0 = 0.0f; wn1 = 0.0f; }   // w-pos >= 128

                const float wwin[8] = {wp2, wp3, w4.x, w4.y, w4.z, w4.w, wn0, wn1};

                #pragma unroll
                for (int n = 0; n < 4; n++) {
                    const float xwin[8] = {xp2[n], xp3[n],
                                           xq[n].x, xq[n].y, xq[n].z, xq[n].w,
                                           xn0[n], xn1[n]};
                    #pragma unroll
                    for (int j = 0; j < 4; j++) {
                        const int k = j + 4 - kw;      // window index, 0..7
                        acc[n][j] = fmaf(wwin[k], xwin[k], acc[n][j]);
                    }
                }
            }
        }
    }

    // ---- reduce the 4 i-slices through smem
    #pragma unroll
    for (int n = 0; n < 4; n++)
        *(float4*)&red[o2][n][ih][4 * q] =
            make_float4(acc[n][0], acc[n][1], acc[n][2], acc[n][3]);
    __syncthreads();

    // 256 writer threads: (o2w:2) x (nw:4) x (qw:32)
    const int o2w = t >> 7;
    const int nw  = (t >> 5) & 3;
    const int qw  = t & 31;
    const int ocw = og * 2 + o2w;

    float4 s0 = *(const float4*)&red[o2w][nw][0][4 * qw];
    float4 s1 = *(const float4*)&red[o2w][nw][1][4 * qw];
    float4 s2 = *(const float4*)&red[o2w][nw][2][4 * qw];
    float4 s3 = *(const float4*)&red[o2w][nw][3][4 * qw];

    const float b = __ldg(bias + ocw);
    float4 r;
    r.x = s0.x + s1.x + s2.x + s3.x + b;
    r.y = s0.y + s1.y + s2.y + s3.y + b;
    r.z = s0.z + s1.z + s2.z + s3.z + b;
    r.w = s0.w + s1.w + s2.w + s3.w + b;

    ((float4*)out)[((nw * 16 + ocw) * H_ + oh) * 32 + qw] = r;
}

extern "C" void kernel_launch(void* const* d_in, const int* in_sizes, int n_in,
                              void* d_out, int out_size)
{
    const float* x    = (const float*)d_in[0];
    const float* wt   = (const float*)d_in[1];
    const float* bias = (const float*)d_in[2];
    float*       out  = (float*)d_out;

    svct_kernel<<<1024, 256>>>(x, wt, bias, out);
}